// round 15
// baseline (speedup 1.0000x reference)
#include <cuda_runtime.h>
#include <math.h>
#include <stdint.h>

constexpr int T_ = 256, B_ = 1024, Y_ = 32, H_ = 1024, R_ = 512, R3_ = 1536;
constexpr int NBLK_ = 148;              // persistent grid: 1 CTA/SM, 256 thr
constexpr int MT16_ALL = T_ * B_ / 16;  // 16384 16-row A-frag tiles

// ---------------- device scratch (static; no allocations) ----------------
// A-fragment layout (uint32 words, bf16x2):
//   block (mtile=m>>4, k16=k>>4), idx = (mtile*NK16 + k16)*128 + lane*4 + r
//   lane = (m&7)*4 + ((k>>1)&3);  r = ((m>>3)&1) + 2*((k>>3)&1)
//   -> per lane ONE contiguous uint4 = the 4 mma.m16n8k16 A regs.
// B-fragment layout (weights; verified in rounds 9-11):
//   idx = (ntile*NK16 + k16)*64 + ((n&7)*4 + ((k>>1)&3))*2 + ((k>>3)&1)
//   -> per lane one uint2 = the 2 B regs.
__device__ uint32_t g_h0f[B_ * R_ / 2];                  // 1 MB
__device__ uint32_t g_h1f[B_ * R_ / 2];
__device__ uint32_t g_yf[(size_t)T_ * B_ * Y_ / 2];      // 16 MB
__device__ uint32_t g_h1allf[(size_t)T_ * B_ * R_ / 2];  // 256 MB
__device__ uint32_t g_d1f[(size_t)T_ * B_ * H_ / 2];     // 512 MB
__device__ uint32_t g_d2f[(size_t)T_ * B_ * H_ / 2];     // 512 MB
__device__ uint32_t g_whh0f[R3_ * R_ / 2];
__device__ uint32_t g_wih0f[R3_ * Y_ / 2];
__device__ uint32_t g_wih1f[R3_ * R_ / 2];
__device__ uint32_t g_whh1f[R3_ * R_ / 2];
__device__ uint32_t g_w1f[H_ * R_ / 2];
__device__ uint32_t g_w2f[H_ * H_ / 2];
__device__ uint32_t g_hwf[64 * H_ / 2];   // head: rows 0-31 mean, 32-63 std
__device__ float g_h0[B_ * R_];
__device__ float g_h1[B_ * R_];
__device__ float g_gi[B_ * R3_];
__device__ float g_gh[B_ * R3_];
__device__ float g_gh1[B_ * R3_];
__device__ float g_ms[(size_t)T_ * B_ * 64];             // 64 MB mean|std
__device__ float g_rowsum[T_ * B_];

// ---------------- software grid barrier (replay-safe) ----------------
__device__ unsigned g_bar_arrive;
__device__ volatile unsigned g_bar_gen;

__device__ __forceinline__ void grid_sync()
{
    __threadfence();
    __syncthreads();
    if (threadIdx.x == 0) {
        unsigned gen = g_bar_gen;
        if (atomicAdd(&g_bar_arrive, 1u) == (unsigned)gridDim.x - 1u) {
            g_bar_arrive = 0u;
            __threadfence();
            g_bar_gen = gen + 1u;
        } else {
            while (g_bar_gen == gen) { __nanosleep(32); }
        }
        __threadfence();
    }
    __syncthreads();
}

// ---------------- helpers ----------------
__device__ __forceinline__ uint32_t packbf(float lo, float hi)
{
    uint32_t u;
    asm("cvt.rn.bf16x2.f32 %0, %1, %2;" : "=r"(u) : "f"(hi), "f"(lo));
    return u;
}
__device__ __forceinline__ void mma_bf16(float* c, const uint4 a, const uint2 b)
{
    asm volatile(
        "mma.sync.aligned.m16n8k16.row.col.f32.bf16.bf16.f32 "
        "{%0,%1,%2,%3}, {%4,%5,%6,%7}, {%8,%9}, {%0,%1,%2,%3};"
        : "+f"(c[0]), "+f"(c[1]), "+f"(c[2]), "+f"(c[3])
        : "r"(a.x), "r"(a.y), "r"(a.z), "r"(a.w), "r"(b.x), "r"(b.y));
}
__device__ __forceinline__ float sigmoid_fast(float x)
{
    float e, r;
    asm("ex2.approx.f32 %0, %1;" : "=f"(e) : "f"(-1.4426950408889634f * x));
    asm("rcp.approx.f32 %0, %1;" : "=f"(r) : "f"(1.f + e));
    return r;
}
__device__ __forceinline__ float tanh_fast(float x)
{
    float r;
    asm("tanh.approx.f32 %0, %1;" : "=f"(r) : "f"(x));
    return r;
}

// ---------------------------------------------------------------
// Register-resident bf16 GEMM over fragment-order global operands.
// Block tile: (WM*MT*16) x (WN*NT*8), 256 threads = WM*WN*? warps.
// No shared memory, no __syncthreads. 2-deep register double buffer.
// ---------------------------------------------------------------
template<int MT, int NT, int WM, int WN>
__device__ __forceinline__ void gemm_frag(
    const uint32_t* __restrict__ Af, const uint32_t* __restrict__ Bf,
    int NK16, int mtile0, int ntile0, float acc[MT][NT][4])
{
    const int lane = threadIdx.x & 31;
    const int wid = threadIdx.x >> 5;
    const int wm = wid / WN, wn = wid % WN;
    const uint4* A4 = reinterpret_cast<const uint4*>(Af);
    const uint2* B2 = reinterpret_cast<const uint2*>(Bf);
    const int am0 = mtile0 + wm * MT;
    const int bn0 = ntile0 + wn * NT;

    uint4 a0[MT], a1[MT];
    uint2 b0[NT], b1[NT];

#define LD_FRAGS(Ar, Br, k16)                                                  \
    {                                                                          \
        _Pragma("unroll")                                                      \
        for (int mt = 0; mt < MT; mt++)                                        \
            Ar[mt] = A4[((size_t)(am0 + mt) * NK16 + (k16)) * 32 + lane];      \
        _Pragma("unroll")                                                      \
        for (int nt = 0; nt < NT; nt++)                                        \
            Br[nt] = B2[((size_t)(bn0 + nt) * NK16 + (k16)) * 32 + lane];      \
    }
#define MMA_ALL(Ar, Br)                                                        \
    {                                                                          \
        _Pragma("unroll")                                                      \
        for (int mt = 0; mt < MT; mt++)                                        \
            _Pragma("unroll")                                                  \
            for (int nt = 0; nt < NT; nt++)                                    \
                mma_bf16(acc[mt][nt], Ar[mt], Br[nt]);                         \
    }

    LD_FRAGS(a0, b0, 0);
#pragma unroll 1
    for (int k = 0; k < NK16; k += 2) {
        LD_FRAGS(a1, b1, k + 1);       // NK16 is always even in all call sites
        MMA_ALL(a0, b0);
        if (k + 2 < NK16) LD_FRAGS(a0, b0, k + 2);
        MMA_ALL(a1, b1);
    }
#undef LD_FRAGS
#undef MMA_ALL
}

// ---- epilogues ----
// fp32 row-major C (+bias): persistent gate pre-activations. MT=2,NT=8,WM=4,WN=2.
__device__ __forceinline__ void epi_f32(
    float acc[2][8][4], const float* __restrict__ bias,
    int bm, int bn, float* __restrict__ C, int ldc)
{
    const int lane = threadIdx.x & 31;
    const int wid = threadIdx.x >> 5;
    const int wm = wid >> 1, wn = wid & 1;
    const int g = lane >> 2, tig = lane & 3;
#pragma unroll
    for (int mt = 0; mt < 2; mt++) {
        const int m0 = bm + (wm * 2 + mt) * 16 + g;
#pragma unroll
        for (int nt = 0; nt < 8; nt++) {
            const int col = bn + (wn * 8 + nt) * 8 + 2 * tig;
            const float bb0 = bias[col], bb1 = bias[col + 1];
            *reinterpret_cast<float2*>(C + (size_t)m0 * ldc + col) =
                make_float2(acc[mt][nt][0] + bb0, acc[mt][nt][1] + bb1);
            *reinterpret_cast<float2*>(C + (size_t)(m0 + 8) * ldc + col) =
                make_float2(acc[mt][nt][2] + bb0, acc[mt][nt][3] + bb1);
        }
    }
}

// ReLU + A-fragment output (decoder): each lane emits its own lane slot
// as one STG.128 per (mt, nt-pair). MT=2,NT=8,WM=4,WN=2.
__device__ __forceinline__ void epi_frag_relu(
    float acc[2][8][4], const float* __restrict__ bias,
    int mtile0, int bn, uint32_t* __restrict__ Of, int NK16o)
{
    const int lane = threadIdx.x & 31;
    const int wid = threadIdx.x >> 5;
    const int wm = wid >> 1, wn = wid & 1;
    const int tig = lane & 3;
    uint4* O4 = reinterpret_cast<uint4*>(Of);
#pragma unroll
    for (int mt = 0; mt < 2; mt++) {
        const int m0t = mtile0 + wm * 2 + mt;
#pragma unroll
        for (int q = 0; q < 4; q++) {
            const int k16o = (bn >> 4) + wn * 4 + q;
            float v[8];
#pragma unroll
            for (int h = 0; h < 2; h++) {       // nt = 2q + h
                const int nt = 2 * q + h;
                const int col = bn + (wn * 8 + nt) * 8 + 2 * tig;
                v[h*4+0] = fmaxf(acc[mt][nt][0] + bias[col], 0.f);
                v[h*4+1] = fmaxf(acc[mt][nt][1] + bias[col + 1], 0.f);
                v[h*4+2] = fmaxf(acc[mt][nt][2] + bias[col], 0.f);
                v[h*4+3] = fmaxf(acc[mt][nt][3] + bias[col + 1], 0.f);
            }
            uint4 w;
            w.x = packbf(v[0], v[1]);   // r0: rows m, k8=0
            w.y = packbf(v[2], v[3]);   // r1: rows m+8, k8=0
            w.z = packbf(v[4], v[5]);   // r2: rows m, k8=1
            w.w = packbf(v[6], v[7]);   // r3: rows m+8, k8=1
            O4[((size_t)m0t * NK16o + k16o) * 32 + lane] = w;
        }
    }
}

// ---------------------------------------------------------------
// GRU gate fuse (grid-stride): fast-math activations; writes fp32 h and
// A-fragment bf16 copy (+ optional h1all slot).
// ---------------------------------------------------------------
__device__ void gate_phase(const float* __restrict__ gi, const float* __restrict__ gh,
                           float* __restrict__ h, uint32_t* __restrict__ hf,
                           uint32_t* __restrict__ slot)
{
    const int stride = gridDim.x * blockDim.x;
    for (int idx = blockIdx.x * blockDim.x + threadIdx.x;
         idx < B_ * R_ / 8; idx += stride) {
        const int b = idx >> 6, jb = idx & 63, j0 = jb << 3;
        const float* gib = gi + (size_t)b * R3_ + j0;
        const float* ghb = gh + (size_t)b * R3_ + j0;
        float* hb = h + (size_t)b * R_ + j0;
        float ir[8], iz[8], in_[8], hr[8], hz[8], hn[8], ho[8], hv[8];
        *(float4*)(ir)      = *(const float4*)(gib);
        *(float4*)(ir + 4)  = *(const float4*)(gib + 4);
        *(float4*)(iz)      = *(const float4*)(gib + R_);
        *(float4*)(iz + 4)  = *(const float4*)(gib + R_ + 4);
        *(float4*)(in_)     = *(const float4*)(gib + 2 * R_);
        *(float4*)(in_ + 4) = *(const float4*)(gib + 2 * R_ + 4);
        *(float4*)(hr)      = *(const float4*)(ghb);
        *(float4*)(hr + 4)  = *(const float4*)(ghb + 4);
        *(float4*)(hz)      = *(const float4*)(ghb + R_);
        *(float4*)(hz + 4)  = *(const float4*)(ghb + R_ + 4);
        *(float4*)(hn)      = *(const float4*)(ghb + 2 * R_);
        *(float4*)(hn + 4)  = *(const float4*)(ghb + 2 * R_ + 4);
        *(float4*)(ho)      = *(const float4*)(hb);
        *(float4*)(ho + 4)  = *(const float4*)(hb + 4);
#pragma unroll
        for (int i = 0; i < 8; i++) {
            const float r = sigmoid_fast(ir[i] + hr[i]);
            const float z = sigmoid_fast(iz[i] + hz[i]);
            const float n = tanh_fast(in_[i] + r * hn[i]);
            hv[i] = (1.f - z) * n + z * ho[i];
        }
        *(float4*)(hb)     = make_float4(hv[0], hv[1], hv[2], hv[3]);
        *(float4*)(hb + 4) = make_float4(hv[4], hv[5], hv[6], hv[7]);
        // A-fragment words: blk = (b>>4)*32 + (j0>>4); lane=(b&7)*4+w; r fixed
        const int blk = (b >> 4) * 32 + (j0 >> 4);
        const int r = ((b >> 3) & 1) + 2 * ((j0 >> 3) & 1);
        const uint32_t base = (uint32_t)blk * 128 + (b & 7) * 16 + r;
        uint32_t w0 = packbf(hv[0], hv[1]), w1 = packbf(hv[2], hv[3]);
        uint32_t w2 = packbf(hv[4], hv[5]), w3 = packbf(hv[6], hv[7]);
        hf[base]      = w0;
        hf[base + 4]  = w1;
        hf[base + 8]  = w2;
        hf[base + 12] = w3;
        if (slot) {
            slot[base]      = w0;
            slot[base + 4]  = w1;
            slot[base + 8]  = w2;
            slot[base + 12] = w3;
        }
    }
}

// ---------------------------------------------------------------
// Persistent recurrence: T=256 scan in one launch. No smem at all.
// P0: 0..95 gh0, 96..191 gh1, 192..287 gi0(K=32). P2: 0..95 gi1.
// ---------------------------------------------------------------
__global__ void __launch_bounds__(256) rnn_persistent(
    const float* __restrict__ bih0, const float* __restrict__ bhh0,
    const float* __restrict__ bih1, const float* __restrict__ bhh1)
{
    const int bid = blockIdx.x;
    for (int t = 0; t < T_; t++) {
        // ---- P0 ----
#pragma unroll 1
        for (int rep = 0; rep < 2; rep++) {
            const int tile = bid + rep * NBLK_;
            if (tile < 288) {
                const int grp = tile / 96, tt = tile % 96;
                const int mt0 = (tt / 12) * 8;      // 16-row units
                const int nt0 = (tt % 12) * 16;     // 8-col units
                float acc[2][8][4];
#pragma unroll
                for (int i = 0; i < 2; i++)
#pragma unroll
                    for (int j = 0; j < 8; j++)
#pragma unroll
                        for (int r = 0; r < 4; r++) acc[i][j][r] = 0.f;
                if (grp == 0) {
                    gemm_frag<2, 8, 4, 2>(g_h0f, g_whh0f, R_ / 16, mt0, nt0, acc);
                    epi_f32(acc, bhh0, mt0 * 16, nt0 * 8, g_gh, R3_);
                } else if (grp == 1) {
                    gemm_frag<2, 8, 4, 2>(g_h1f, g_whh1f, R_ / 16, mt0, nt0, acc);
                    epi_f32(acc, bhh1, mt0 * 16, nt0 * 8, g_gh1, R3_);
                } else {
                    gemm_frag<2, 8, 4, 2>(g_yf + (size_t)t * (B_ * Y_ / 2),
                                          g_wih0f, Y_ / 16, mt0, nt0, acc);
                    epi_f32(acc, bih0, mt0 * 16, nt0 * 8, g_gi, R3_);
                }
            }
        }
        grid_sync();
        // ---- P1: gate layer 0 ----
        gate_phase(g_gi, g_gh, g_h0, g_h0f, nullptr);
        grid_sync();
        // ---- P2: gi1 = h0' @ wih1^T ----
        if (bid < 96) {
            const int mt0 = (bid / 12) * 8;
            const int nt0 = (bid % 12) * 16;
            float acc[2][8][4];
#pragma unroll
            for (int i = 0; i < 2; i++)
#pragma unroll
                for (int j = 0; j < 8; j++)
#pragma unroll
                    for (int r = 0; r < 4; r++) acc[i][j][r] = 0.f;
            gemm_frag<2, 8, 4, 2>(g_h0f, g_wih1f, R_ / 16, mt0, nt0, acc);
            epi_f32(acc, bih1, mt0 * 16, nt0 * 8, g_gi, R3_);
        }
        grid_sync();
        // ---- P3: gate layer 1 (+ h1all slot t+1) ----
        uint32_t* slot = (t + 1 < T_)
            ? (g_h1allf + (size_t)(t + 1) * (B_ * R_ / 2)) : nullptr;
        gate_phase(g_gi, g_gh1, g_h1, g_h1f, slot);
        grid_sync();
    }
}

// ---------------------------------------------------------------
// Decoder GEMM: relu(A@W^T+b) -> A-fragment output. grid=(8, 2048), 256 thr.
__global__ void __launch_bounds__(256) dec_gemm(
    const uint32_t* __restrict__ Af, const uint32_t* __restrict__ Bf,
    const float* __restrict__ bias, uint32_t* __restrict__ Of,
    int NK16, int NK16o)
{
    const int mt0 = blockIdx.y * 8;
    const int nt0 = blockIdx.x * 16;
    float acc[2][8][4];
#pragma unroll
    for (int i = 0; i < 2; i++)
#pragma unroll
        for (int j = 0; j < 8; j++)
#pragma unroll
            for (int r = 0; r < 4; r++) acc[i][j][r] = 0.f;
    gemm_frag<2, 8, 4, 2>(Af, Bf, NK16, mt0, nt0, acc);
    epi_frag_relu(acc, bias, mt0, nt0 * 8, Of, NK16o);
}

// Head GEMM: ms[row][0..63] = d2 @ [mean_w; std_w]^T (+split bias).
// grid = 2048, 256 thr: WM=8, WN=1, MT=1, NT=8 (BM=128, BN=64).
__global__ void __launch_bounds__(256) head_gemm(
    const float* __restrict__ mb, const float* __restrict__ sbv)
{
    const int mt0 = blockIdx.x * 8;
    float acc[1][8][4];
#pragma unroll
    for (int j = 0; j < 8; j++)
#pragma unroll
        for (int r = 0; r < 4; r++) acc[0][j][r] = 0.f;
    gemm_frag<1, 8, 8, 1>(g_d2f, g_hwf, H_ / 16, mt0, 0, acc);

    const int lane = threadIdx.x & 31;
    const int wm = threadIdx.x >> 5;
    const int g = lane >> 2, tig = lane & 3;
    const int m0 = mt0 * 16 + wm * 16 + g;
    float* row = g_ms + (size_t)m0 * 64;
#pragma unroll
    for (int nt = 0; nt < 8; nt++) {
        const int col = nt * 8 + 2 * tig;
        const float bb0 = (col < 32) ? mb[col] : sbv[col - 32];
        const float bb1 = (col + 1 < 32) ? mb[col + 1] : sbv[col + 1 - 32];
        *reinterpret_cast<float2*>(row + col) =
            make_float2(acc[0][nt][0] + bb0, acc[0][nt][1] + bb1);
        *reinterpret_cast<float2*>(row + 8 * 64 + col) =
            make_float2(acc[0][nt][2] + bb0, acc[0][nt][3] + bb1);
    }
}

// NLL per row (one warp/row), then deterministic reduce.
__global__ void __launch_bounds__(256) nll_kernel(const float* __restrict__ y)
{
    const int row = blockIdx.x * 8 + (threadIdx.x >> 5);
    const int lane = threadIdx.x & 31;
    const float* m = g_ms + (size_t)row * 64;
    const float mean = m[lane];
    const float sraw = m[32 + lane];
    const float stdv = (sraw > 20.f) ? sraw : log1pf(expf(sraw));
    const float yv = y[(size_t)row * Y_ + lane];
    const float diff = yv - mean;
    float term = diff * diff / (stdv * stdv) + 2.f * logf(stdv)
                 + 1.8378770664093453f;
#pragma unroll
    for (int o = 16; o > 0; o >>= 1)
        term += __shfl_down_sync(0xffffffffu, term, o);
    if (lane == 0) g_rowsum[row] = 0.5f * term;
}

__global__ void __launch_bounds__(1024) reduce_kernel(float* __restrict__ out)
{
    __shared__ double sh[1024];
    double s = 0.0;
    for (int i = threadIdx.x; i < T_ * B_; i += 1024)
        s += (double)g_rowsum[i];
    sh[threadIdx.x] = s;
    __syncthreads();
    for (int o = 512; o > 0; o >>= 1) {
        if (threadIdx.x < o) sh[threadIdx.x] += sh[threadIdx.x + o];
        __syncthreads();
    }
    if (threadIdx.x == 0) out[0] = (float)sh[0];
}

// ---------------- prepacks ----------------
// W[N x K] fp32 -> bf16 B-fragment order (verified layout).
__global__ void prepack_w(const float* __restrict__ W, uint32_t* __restrict__ out,
                          int N, int K)
{
    const int idx = blockIdx.x * blockDim.x + threadIdx.x;
    if (idx >= N * K / 2) return;
    const int n = idx / (K / 2), p = idx % (K / 2);
    const int k = p * 2;
    const uint32_t w = packbf(W[(size_t)n * K + k], W[(size_t)n * K + k + 1]);
    out[((size_t)(n >> 3) * (K / 16) + (p >> 3)) * 64
        + ((n & 7) * 4 + (p & 3)) * 2 + ((p >> 2) & 1)] = w;
}

// head weights: rows 0-31 = mean_w, 32-63 = std_w; B-frag, K=1024.
__global__ void prepack_head(const float* __restrict__ mw, const float* __restrict__ sw)
{
    const int idx = blockIdx.x * blockDim.x + threadIdx.x;
    if (idx >= 64 * H_ / 2) return;
    const int n = idx >> 9, p = idx & 511, k = p * 2;
    const float* src = (n < 32) ? (mw + (size_t)n * H_) : (sw + (size_t)(n - 32) * H_);
    g_hwf[((size_t)(n >> 3) * 64 + (p >> 3)) * 64
          + ((n & 7) * 4 + (p & 3)) * 2 + ((p >> 2) & 1)] = packbf(src[k], src[k + 1]);
}

// y[T][B][32] -> A-fragment order (NK16 = 2 per timestep).
__global__ void prepack_y(const float* __restrict__ y)
{
    const int idx = blockIdx.x * blockDim.x + threadIdx.x;
    if (idx >= T_ * B_ * 16) return;
    const int p = idx & 15, b = (idx >> 4) & 1023, t = idx >> 14;
    const float* yp = y + ((size_t)t * B_ + b) * Y_ + p * 2;
    const int blk = (t * 64 + (b >> 4)) * 2 + (p >> 3);
    const int lane = (b & 7) * 4 + (p & 3);
    const int r = ((b >> 3) & 1) + 2 * ((p >> 2) & 1);
    g_yf[(size_t)blk * 128 + lane * 4 + r] = packbf(yp[0], yp[1]);
}

__global__ void init_kernel()
{
    const int idx = blockIdx.x * blockDim.x + threadIdx.x;
    if (idx < B_ * R_) { g_h0[idx] = 0.f; g_h1[idx] = 0.f; }
    if (idx < B_ * R_ / 2) {
        g_h0f[idx] = 0u; g_h1f[idx] = 0u; g_h1allf[idx] = 0u;  // slot t=0
    }
}

// ---------------------------------------------------------------
extern "C" void kernel_launch(void* const* d_in, const int* in_sizes, int n_in,
                              void* d_out, int out_size)
{
    const float* y      = (const float*)d_in[0];
    const float* dec_w1 = (const float*)d_in[1];
    const float* dec_b1 = (const float*)d_in[2];
    const float* dec_w2 = (const float*)d_in[3];
    const float* dec_b2 = (const float*)d_in[4];
    const float* mean_w = (const float*)d_in[5];
    const float* mean_b = (const float*)d_in[6];
    const float* std_w  = (const float*)d_in[7];
    const float* std_b  = (const float*)d_in[8];
    const float* wih0   = (const float*)d_in[9];
    const float* whh0   = (const float*)d_in[10];
    const float* bih0   = (const float*)d_in[11];
    const float* bhh0   = (const float*)d_in[12];
    const float* wih1   = (const float*)d_in[13];
    const float* whh1   = (const float*)d_in[14];
    const float* bih1   = (const float*)d_in[15];
    const float* bhh1   = (const float*)d_in[16];
    float* out = (float*)d_out;

    uint32_t *pwhh0, *pwih0, *pwih1, *pwhh1, *pw1, *pw2, *ph1all, *pd1, *pd2;
    cudaGetSymbolAddress((void**)&pwhh0, g_whh0f);
    cudaGetSymbolAddress((void**)&pwih0, g_wih0f);
    cudaGetSymbolAddress((void**)&pwih1, g_wih1f);
    cudaGetSymbolAddress((void**)&pwhh1, g_whh1f);
    cudaGetSymbolAddress((void**)&pw1, g_w1f);
    cudaGetSymbolAddress((void**)&pw2, g_w2f);
    cudaGetSymbolAddress((void**)&ph1all, g_h1allf);
    cudaGetSymbolAddress((void**)&pd1, g_d1f);
    cudaGetSymbolAddress((void**)&pd2, g_d2f);

    auto blk = [](int n) { return (n + 255) / 256; };
    prepack_w<<<blk(R3_ * R_ / 2), 256>>>(whh0, pwhh0, R3_, R_);
    prepack_w<<<blk(R3_ * Y_ / 2), 256>>>(wih0, pwih0, R3_, Y_);
    prepack_w<<<blk(R3_ * R_ / 2), 256>>>(wih1, pwih1, R3_, R_);
    prepack_w<<<blk(R3_ * R_ / 2), 256>>>(whh1, pwhh1, R3_, R_);
    prepack_w<<<blk(H_ * R_ / 2), 256>>>(dec_w1, pw1, H_, R_);
    prepack_w<<<blk(H_ * H_ / 2), 256>>>(dec_w2, pw2, H_, H_);
    prepack_head<<<blk(64 * H_ / 2), 256>>>(mean_w, std_w);
    prepack_y<<<blk(T_ * B_ * 16), 256>>>(y);
    init_kernel<<<blk(B_ * R_), 256>>>();

    // sequential scan: one persistent kernel
    rnn_persistent<<<NBLK_, 256>>>(bih0, bhh0, bih1, bhh1);

    // decoder + head over ALL timesteps (single launches)
    dec_gemm<<<dim3(8, MT16_ALL / 8), 256>>>(ph1all, pw1, dec_b1, pd1,
                                             R_ / 16, H_ / 16);
    dec_gemm<<<dim3(8, MT16_ALL / 8), 256>>>(pd1, pw2, dec_b2, pd2,
                                             H_ / 16, H_ / 16);
    head_gemm<<<MT16_ALL / 8, 256>>>(mean_b, std_b);
    nll_kernel<<<T_ * B_ / 8, 256>>>(y);
    reduce_kernel<<<1, 1024>>>(out);
}

// round 17
// speedup vs baseline: 1.5521x; 1.5521x over previous
#include <cuda_runtime.h>
#include <math.h>
#include <stdint.h>

constexpr int T_ = 256, B_ = 1024, Y_ = 32, H_ = 1024, R_ = 512, R3_ = 1536;
constexpr int NBLK_ = 296;              // persistent grid: 2 CTA/SM
constexpr int MT16_ALL = T_ * B_ / 16;  // 16384 16-row A-frag tiles

// ---------------- device scratch (static; no allocations) ----------------
// A-fragment layout (uint32 words, bf16x2):
//   block (mtile=m>>4, k16=k>>4): idx = (mtile*NK16 + k16)*128 + lane*4 + r
//   lane = (m&7)*4 + ((k>>1)&3);  r = ((m>>3)&1) + 2*((k>>3)&1)
// B-fragment layout (weights):
//   idx = (ntile*NK16 + k16)*64 + ((n&7)*4 + ((k>>1)&3))*2 + ((k>>3)&1)
__device__ uint32_t g_h0f[B_ * R_ / 2];
__device__ uint32_t g_h1f[B_ * R_ / 2];
__device__ uint32_t g_yf[(size_t)T_ * B_ * Y_ / 2];
__device__ uint32_t g_h1allf[(size_t)T_ * B_ * R_ / 2];
__device__ uint32_t g_d1f[(size_t)T_ * B_ * H_ / 2];
__device__ uint32_t g_d2f[(size_t)T_ * B_ * H_ / 2];
__device__ uint32_t g_whh0f[R3_ * R_ / 2];
__device__ uint32_t g_wih0f[R3_ * Y_ / 2];
__device__ uint32_t g_wih1f[R3_ * R_ / 2];
__device__ uint32_t g_whh1f[R3_ * R_ / 2];
__device__ uint32_t g_w1f[H_ * R_ / 2];
__device__ uint32_t g_w2f[H_ * H_ / 2];
__device__ uint32_t g_hwf[64 * H_ / 2];
__device__ float g_h0[B_ * R_];
__device__ float g_h1[B_ * R_];
__device__ float g_gi[B_ * R3_];
__device__ float g_gh[B_ * R3_];
__device__ float g_gh1[B_ * R3_];
__device__ float g_ms[(size_t)T_ * B_ * 64];
__device__ float g_rowsum[T_ * B_];

// ---------------- software grid barrier (replay-safe) ----------------
__device__ unsigned g_bar_arrive;
__device__ volatile unsigned g_bar_gen;

__device__ __forceinline__ void grid_sync()
{
    __threadfence();
    __syncthreads();
    if (threadIdx.x == 0) {
        unsigned gen = g_bar_gen;
        if (atomicAdd(&g_bar_arrive, 1u) == (unsigned)gridDim.x - 1u) {
            g_bar_arrive = 0u;
            __threadfence();
            g_bar_gen = gen + 1u;
        } else {
            while (g_bar_gen == gen) { __nanosleep(32); }
        }
        __threadfence();
    }
    __syncthreads();
}

// ---------------- helpers ----------------
__device__ __forceinline__ uint32_t packbf(float lo, float hi)
{
    uint32_t u;
    asm("cvt.rn.bf16x2.f32 %0, %1, %2;" : "=r"(u) : "f"(hi), "f"(lo));
    return u;
}
__device__ __forceinline__ void mma_bf16(float* c, const uint4 a, const uint2 b)
{
    asm volatile(
        "mma.sync.aligned.m16n8k16.row.col.f32.bf16.bf16.f32 "
        "{%0,%1,%2,%3}, {%4,%5,%6,%7}, {%8,%9}, {%0,%1,%2,%3};"
        : "+f"(c[0]), "+f"(c[1]), "+f"(c[2]), "+f"(c[3])
        : "r"(a.x), "r"(a.y), "r"(a.z), "r"(a.w), "r"(b.x), "r"(b.y));
}
__device__ __forceinline__ float sigmoid_fast(float x)
{
    float e, r;
    asm("ex2.approx.f32 %0, %1;" : "=f"(e) : "f"(-1.4426950408889634f * x));
    asm("rcp.approx.f32 %0, %1;" : "=f"(r) : "f"(1.f + e));
    return r;
}
__device__ __forceinline__ float tanh_fast(float x)
{
    float r;
    asm("tanh.approx.f32 %0, %1;" : "=f"(r) : "f"(x));
    return r;
}
__device__ __forceinline__ void cp_async16(void* smem_dst, const void* gsrc)
{
    const uint32_t d = (uint32_t)__cvta_generic_to_shared(smem_dst);
    asm volatile("cp.async.ca.shared.global [%0], [%1], 16;"
                 :: "r"(d), "l"(gsrc) : "memory");
}
__device__ __forceinline__ void cp_commit()
{
    asm volatile("cp.async.commit_group;" ::: "memory");
}
__device__ __forceinline__ void cp_wait2()
{
    asm volatile("cp.async.wait_group 2;" ::: "memory");
}
__device__ __forceinline__ void cp_wait0()
{
    asm volatile("cp.async.wait_group 0;" ::: "memory");
}

// ---------------------------------------------------------------
// cp.async 3-stage pipelined bf16 GEMM over fragment-order operands.
// Block tile (WM*MT*16) x (WN*NT*8), 256 threads, stage = 2 k16 (32 K).
// smem per stage: A 512 u4 (8 mtiles x 2 k16 x 32) + B NTILES*32 u4.
// Fragment loads: A one LDS.128/lane, B one LDS.64/lane, conflict-free.
// ---------------------------------------------------------------
template<int MT, int NT, int WM, int WN>
__device__ __forceinline__ void gemm_cp(
    const uint4* __restrict__ A4, const uint4* __restrict__ B4,
    int NK16, int mtile0, int ntile0, uint4* __restrict__ sm,
    float acc[MT][NT][4])
{
    constexpr int NTILES = WN * NT;          // 16 (dec) or 8 (head)
    constexpr int A_U4 = 512;
    constexpr int B_U4 = NTILES * 32;        // 512 or 256
    constexpr int ST_U4 = A_U4 + B_U4;
    constexpr int A_CP = A_U4 / 256;         // 2
    constexpr int B_CP = B_U4 / 256;         // 2 or 1

    const int tid = threadIdx.x;
    const int lane = tid & 31;
    const int wid = tid >> 5;
    const int wm = wid / WN, wn = wid % WN;
    const int nst = NK16 >> 1;

    auto issue = [&](int s) {
        uint4* dst = sm + (s % 3) * ST_U4;
        const int k0 = s * 2;
#pragma unroll
        for (int i = 0; i < A_CP; i++) {
            const int u = tid + i * 256;
            const int b = u >> 5, off = u & 31;
            cp_async16(dst + u,
                A4 + ((size_t)(mtile0 + (b >> 1)) * NK16 + k0 + (b & 1)) * 32 + off);
        }
#pragma unroll
        for (int i = 0; i < B_CP; i++) {
            const int u = tid + i * 256;
            const int b = u >> 4, off = u & 15;
            cp_async16(dst + A_U4 + u,
                B4 + ((size_t)(ntile0 + (b >> 1)) * NK16 + k0 + (b & 1)) * 16 + off);
        }
        cp_commit();
    };

    const int pre = nst < 3 ? nst : 3;
    for (int s = 0; s < pre; s++) issue(s);

#pragma unroll 1
    for (int s = 0; s < nst; s++) {
        if (s + 3 <= nst) cp_wait2(); else cp_wait0();
        __syncthreads();
        const uint4* abuf = sm + (s % 3) * ST_U4;
        const uint2* bbuf = reinterpret_cast<const uint2*>(abuf + A_U4);
#pragma unroll
        for (int kl = 0; kl < 2; kl++) {
            uint4 a[MT];
            uint2 b[NT];
#pragma unroll
            for (int mt = 0; mt < MT; mt++)
                a[mt] = abuf[((wm * MT + mt) * 2 + kl) * 32 + lane];
#pragma unroll
            for (int nt = 0; nt < NT; nt++)
                b[nt] = bbuf[((wn * NT + nt) * 2 + kl) * 32 + lane];
#pragma unroll
            for (int mt = 0; mt < MT; mt++)
#pragma unroll
                for (int nt = 0; nt < NT; nt++)
                    mma_bf16(acc[mt][nt], a[mt], b[nt]);
        }
        __syncthreads();               // stage buffer safe to overwrite
        if (s + 3 < nst) issue(s + 3);
    }
}

// ---- epilogues (verified in rounds 12-15) ----
// fp32 row-major C (+bias). MT=2,NT=8,WM=4,WN=2.
__device__ __forceinline__ void epi_f32(
    float acc[2][8][4], const float* __restrict__ bias,
    int bm, int bn, float* __restrict__ C, int ldc)
{
    const int lane = threadIdx.x & 31;
    const int wid = threadIdx.x >> 5;
    const int wm = wid >> 1, wn = wid & 1;
    const int g = lane >> 2, tig = lane & 3;
#pragma unroll
    for (int mt = 0; mt < 2; mt++) {
        const int m0 = bm + (wm * 2 + mt) * 16 + g;
#pragma unroll
        for (int nt = 0; nt < 8; nt++) {
            const int col = bn + (wn * 8 + nt) * 8 + 2 * tig;
            const float bb0 = bias[col], bb1 = bias[col + 1];
            *reinterpret_cast<float2*>(C + (size_t)m0 * ldc + col) =
                make_float2(acc[mt][nt][0] + bb0, acc[mt][nt][1] + bb1);
            *reinterpret_cast<float2*>(C + (size_t)(m0 + 8) * ldc + col) =
                make_float2(acc[mt][nt][2] + bb0, acc[mt][nt][3] + bb1);
        }
    }
}

// ReLU + A-fragment output. MT=2,NT=8,WM=4,WN=2.
__device__ __forceinline__ void epi_frag_relu(
    float acc[2][8][4], const float* __restrict__ bias,
    int mtile0, int bn, uint32_t* __restrict__ Of, int NK16o)
{
    const int lane = threadIdx.x & 31;
    const int wid = threadIdx.x >> 5;
    const int wm = wid >> 1, wn = wid & 1;
    const int tig = lane & 3;
    uint4* O4 = reinterpret_cast<uint4*>(Of);
#pragma unroll
    for (int mt = 0; mt < 2; mt++) {
        const int m0t = mtile0 + wm * 2 + mt;
#pragma unroll
        for (int q = 0; q < 4; q++) {
            const int k16o = (bn >> 4) + wn * 4 + q;
            float v[8];
#pragma unroll
            for (int h = 0; h < 2; h++) {
                const int nt = 2 * q + h;
                const int col = bn + (wn * 8 + nt) * 8 + 2 * tig;
                v[h*4+0] = fmaxf(acc[mt][nt][0] + bias[col], 0.f);
                v[h*4+1] = fmaxf(acc[mt][nt][1] + bias[col + 1], 0.f);
                v[h*4+2] = fmaxf(acc[mt][nt][2] + bias[col], 0.f);
                v[h*4+3] = fmaxf(acc[mt][nt][3] + bias[col + 1], 0.f);
            }
            uint4 w;
            w.x = packbf(v[0], v[1]);
            w.y = packbf(v[2], v[3]);
            w.z = packbf(v[4], v[5]);
            w.w = packbf(v[6], v[7]);
            O4[((size_t)m0t * NK16o + k16o) * 32 + lane] = w;
        }
    }
}

// ---------------------------------------------------------------
// GRU gate fuse (grid-stride): fast-math; writes fp32 h + A-frag bf16 copy.
// ---------------------------------------------------------------
__device__ void gate_phase(const float* __restrict__ gi, const float* __restrict__ gh,
                           float* __restrict__ h, uint32_t* __restrict__ hf,
                           uint32_t* __restrict__ slot)
{
    const int stride = gridDim.x * blockDim.x;
    for (int idx = blockIdx.x * blockDim.x + threadIdx.x;
         idx < B_ * R_ / 8; idx += stride) {
        const int b = idx >> 6, jb = idx & 63, j0 = jb << 3;
        const float* gib = gi + (size_t)b * R3_ + j0;
        const float* ghb = gh + (size_t)b * R3_ + j0;
        float* hb = h + (size_t)b * R_ + j0;
        float ir[8], iz[8], in_[8], hr[8], hz[8], hn[8], ho[8], hv[8];
        *(float4*)(ir)      = *(const float4*)(gib);
        *(float4*)(ir + 4)  = *(const float4*)(gib + 4);
        *(float4*)(iz)      = *(const float4*)(gib + R_);
        *(float4*)(iz + 4)  = *(const float4*)(gib + R_ + 4);
        *(float4*)(in_)     = *(const float4*)(gib + 2 * R_);
        *(float4*)(in_ + 4) = *(const float4*)(gib + 2 * R_ + 4);
        *(float4*)(hr)      = *(const float4*)(ghb);
        *(float4*)(hr + 4)  = *(const float4*)(ghb + 4);
        *(float4*)(hz)      = *(const float4*)(ghb + R_);
        *(float4*)(hz + 4)  = *(const float4*)(ghb + R_ + 4);
        *(float4*)(hn)      = *(const float4*)(ghb + 2 * R_);
        *(float4*)(hn + 4)  = *(const float4*)(ghb + 2 * R_ + 4);
        *(float4*)(ho)      = *(const float4*)(hb);
        *(float4*)(ho + 4)  = *(const float4*)(hb + 4);
#pragma unroll
        for (int i = 0; i < 8; i++) {
            const float r = sigmoid_fast(ir[i] + hr[i]);
            const float z = sigmoid_fast(iz[i] + hz[i]);
            const float n = tanh_fast(in_[i] + r * hn[i]);
            hv[i] = (1.f - z) * n + z * ho[i];
        }
        *(float4*)(hb)     = make_float4(hv[0], hv[1], hv[2], hv[3]);
        *(float4*)(hb + 4) = make_float4(hv[4], hv[5], hv[6], hv[7]);
        const int blk = (b >> 4) * 32 + (j0 >> 4);
        const int r = ((b >> 3) & 1) + 2 * ((j0 >> 3) & 1);
        const uint32_t base = (uint32_t)blk * 128 + (b & 7) * 16 + r;
        uint32_t w0 = packbf(hv[0], hv[1]), w1 = packbf(hv[2], hv[3]);
        uint32_t w2 = packbf(hv[4], hv[5]), w3 = packbf(hv[6], hv[7]);
        hf[base]      = w0;
        hf[base + 4]  = w1;
        hf[base + 8]  = w2;
        hf[base + 12] = w3;
        if (slot) {
            slot[base]      = w0;
            slot[base + 4]  = w1;
            slot[base + 8]  = w2;
            slot[base + 12] = w3;
        }
    }
}

// ---------------------------------------------------------------
// Persistent recurrence: T=256 scan in one launch, 296 blocks (2/SM).
// P0: 0..95 gh0, 96..191 gh1, 192..287 gi0(K=32) -> ONE tile-slot.
// P2: 0..95 gi1.
// ---------------------------------------------------------------
__global__ void __launch_bounds__(256, 2) rnn_persistent(
    const float* __restrict__ bih0, const float* __restrict__ bhh0,
    const float* __restrict__ bih1, const float* __restrict__ bhh1)
{
    __shared__ uint4 sm[3 * 1024];          // 48 KB: 3 stages x (A 512 + B 512)
    const int bid = blockIdx.x;

    for (int t = 0; t < T_; t++) {
        // ---- P0 ----
        if (bid < 288) {
            const int grp = bid / 96, tt = bid % 96;
            const int mt0 = (tt / 12) * 8;
            const int nt0 = (tt % 12) * 16;
            float acc[2][8][4];
#pragma unroll
            for (int i = 0; i < 2; i++)
#pragma unroll
                for (int j = 0; j < 8; j++)
#pragma unroll
                    for (int r = 0; r < 4; r++) acc[i][j][r] = 0.f;
            if (grp == 0) {
                gemm_cp<2, 8, 4, 2>((const uint4*)g_h0f, (const uint4*)g_whh0f,
                                    R_ / 16, mt0, nt0, sm, acc);
                epi_f32(acc, bhh0, mt0 * 16, nt0 * 8, g_gh, R3_);
            } else if (grp == 1) {
                gemm_cp<2, 8, 4, 2>((const uint4*)g_h1f, (const uint4*)g_whh1f,
                                    R_ / 16, mt0, nt0, sm, acc);
                epi_f32(acc, bhh1, mt0 * 16, nt0 * 8, g_gh1, R3_);
            } else {
                gemm_cp<2, 8, 4, 2>((const uint4*)(g_yf + (size_t)t * (B_ * Y_ / 2)),
                                    (const uint4*)g_wih0f, Y_ / 16, mt0, nt0, sm, acc);
                epi_f32(acc, bih0, mt0 * 16, nt0 * 8, g_gi, R3_);
            }
        }
        grid_sync();
        // ---- P1: gate layer 0 ----
        gate_phase(g_gi, g_gh, g_h0, g_h0f, nullptr);
        grid_sync();
        // ---- P2: gi1 = h0' @ wih1^T ----
        if (bid < 96) {
            const int mt0 = (bid / 12) * 8;
            const int nt0 = (bid % 12) * 16;
            float acc[2][8][4];
#pragma unroll
            for (int i = 0; i < 2; i++)
#pragma unroll
                for (int j = 0; j < 8; j++)
#pragma unroll
                    for (int r = 0; r < 4; r++) acc[i][j][r] = 0.f;
            gemm_cp<2, 8, 4, 2>((const uint4*)g_h0f, (const uint4*)g_wih1f,
                                R_ / 16, mt0, nt0, sm, acc);
            epi_f32(acc, bih1, mt0 * 16, nt0 * 8, g_gi, R3_);
        }
        grid_sync();
        // ---- P3: gate layer 1 (+ h1all slot t+1) ----
        uint32_t* slot = (t + 1 < T_)
            ? (g_h1allf + (size_t)(t + 1) * (B_ * R_ / 2)) : nullptr;
        gate_phase(g_gi, g_gh1, g_h1, g_h1f, slot);
        grid_sync();
    }
}

// ---------------------------------------------------------------
// Decoder GEMM: relu(A@W^T+b) -> A-fragment output. grid=(8, 2048).
__global__ void __launch_bounds__(256, 2) dec_gemm(
    const uint32_t* __restrict__ Af, const uint32_t* __restrict__ Bf,
    const float* __restrict__ bias, uint32_t* __restrict__ Of,
    int NK16, int NK16o)
{
    __shared__ uint4 sm[3 * 1024];
    const int mt0 = blockIdx.y * 8;
    const int nt0 = blockIdx.x * 16;
    float acc[2][8][4];
#pragma unroll
    for (int i = 0; i < 2; i++)
#pragma unroll
        for (int j = 0; j < 8; j++)
#pragma unroll
            for (int r = 0; r < 4; r++) acc[i][j][r] = 0.f;
    gemm_cp<2, 8, 4, 2>((const uint4*)Af, (const uint4*)Bf, NK16, mt0, nt0, sm, acc);
    epi_frag_relu(acc, bias, mt0, nt0 * 8, Of, NK16o);
}

// Head GEMM: ms[row][0..63] = d2 @ [mean_w; std_w]^T (+split bias). grid=2048.
// WM=8, WN=1, MT=1, NT=8 (BM=128, BN=64).
__global__ void __launch_bounds__(256, 2) head_gemm(
    const float* __restrict__ mb, const float* __restrict__ sbv)
{
    __shared__ uint4 sm[3 * (512 + 256)];   // 36 KB
    const int mt0 = blockIdx.x * 8;
    float acc[1][8][4];
#pragma unroll
    for (int j = 0; j < 8; j++)
#pragma unroll
        for (int r = 0; r < 4; r++) acc[0][j][r] = 0.f;
    gemm_cp<1, 8, 8, 1>((const uint4*)g_d2f, (const uint4*)g_hwf,
                        H_ / 16, mt0, 0, sm, acc);

    const int lane = threadIdx.x & 31;
    const int wm = threadIdx.x >> 5;
    const int g = lane >> 2, tig = lane & 3;
    const int m0 = mt0 * 16 + wm * 16 + g;
    float* row = g_ms + (size_t)m0 * 64;
#pragma unroll
    for (int nt = 0; nt < 8; nt++) {
        const int col = nt * 8 + 2 * tig;
        const float bb0 = (col < 32) ? mb[col] : sbv[col - 32];
        const float bb1 = (col + 1 < 32) ? mb[col + 1] : sbv[col + 1 - 32];
        *reinterpret_cast<float2*>(row + col) =
            make_float2(acc[0][nt][0] + bb0, acc[0][nt][1] + bb1);
        *reinterpret_cast<float2*>(row + 8 * 64 + col) =
            make_float2(acc[0][nt][2] + bb0, acc[0][nt][3] + bb1);
    }
}

// NLL per row (one warp/row), then deterministic reduce.
__global__ void __launch_bounds__(256) nll_kernel(const float* __restrict__ y)
{
    const int row = blockIdx.x * 8 + (threadIdx.x >> 5);
    const int lane = threadIdx.x & 31;
    const float* m = g_ms + (size_t)row * 64;
    const float mean = m[lane];
    const float sraw = m[32 + lane];
    const float stdv = (sraw > 20.f) ? sraw : log1pf(expf(sraw));
    const float yv = y[(size_t)row * Y_ + lane];
    const float diff = yv - mean;
    float term = diff * diff / (stdv * stdv) + 2.f * logf(stdv)
                 + 1.8378770664093453f;
#pragma unroll
    for (int o = 16; o > 0; o >>= 1)
        term += __shfl_down_sync(0xffffffffu, term, o);
    if (lane == 0) g_rowsum[row] = 0.5f * term;
}

__global__ void __launch_bounds__(1024) reduce_kernel(float* __restrict__ out)
{
    __shared__ double sh[1024];
    double s = 0.0;
    for (int i = threadIdx.x; i < T_ * B_; i += 1024)
        s += (double)g_rowsum[i];
    sh[threadIdx.x] = s;
    __syncthreads();
    for (int o = 512; o > 0; o >>= 1) {
        if (threadIdx.x < o) sh[threadIdx.x] += sh[threadIdx.x + o];
        __syncthreads();
    }
    if (threadIdx.x == 0) out[0] = (float)sh[0];
}

// ---------------- prepacks (verified) ----------------
__global__ void prepack_w(const float* __restrict__ W, uint32_t* __restrict__ out,
                          int N, int K)
{
    const int idx = blockIdx.x * blockDim.x + threadIdx.x;
    if (idx >= N * K / 2) return;
    const int n = idx / (K / 2), p = idx % (K / 2);
    const int k = p * 2;
    const uint32_t w = packbf(W[(size_t)n * K + k], W[(size_t)n * K + k + 1]);
    out[((size_t)(n >> 3) * (K / 16) + (p >> 3)) * 64
        + ((n & 7) * 4 + (p & 3)) * 2 + ((p >> 2) & 1)] = w;
}

__global__ void prepack_head(const float* __restrict__ mw, const float* __restrict__ sw)
{
    const int idx = blockIdx.x * blockDim.x + threadIdx.x;
    if (idx >= 64 * H_ / 2) return;
    const int n = idx >> 9, p = idx & 511, k = p * 2;
    const float* src = (n < 32) ? (mw + (size_t)n * H_) : (sw + (size_t)(n - 32) * H_);
    g_hwf[((size_t)(n >> 3) * 64 + (p >> 3)) * 64
          + ((n & 7) * 4 + (p & 3)) * 2 + ((p >> 2) & 1)] = packbf(src[k], src[k + 1]);
}

__global__ void prepack_y(const float* __restrict__ y)
{
    const int idx = blockIdx.x * blockDim.x + threadIdx.x;
    if (idx >= T_ * B_ * 16) return;
    const int p = idx & 15, b = (idx >> 4) & 1023, t = idx >> 14;
    const float* yp = y + ((size_t)t * B_ + b) * Y_ + p * 2;
    const int blk = (t * 64 + (b >> 4)) * 2 + (p >> 3);
    const int lane = (b & 7) * 4 + (p & 3);
    const int r = ((b >> 3) & 1) + 2 * ((p >> 2) & 1);
    g_yf[(size_t)blk * 128 + lane * 4 + r] = packbf(yp[0], yp[1]);
}

__global__ void init_kernel()
{
    const int idx = blockIdx.x * blockDim.x + threadIdx.x;
    if (idx < B_ * R_) { g_h0[idx] = 0.f; g_h1[idx] = 0.f; }
    if (idx < B_ * R_ / 2) {
        g_h0f[idx] = 0u; g_h1f[idx] = 0u; g_h1allf[idx] = 0u;
    }
}

// ---------------------------------------------------------------
extern "C" void kernel_launch(void* const* d_in, const int* in_sizes, int n_in,
                              void* d_out, int out_size)
{
    const float* y      = (const float*)d_in[0];
    const float* dec_w1 = (const float*)d_in[1];
    const float* dec_b1 = (const float*)d_in[2];
    const float* dec_w2 = (const float*)d_in[3];
    const float* dec_b2 = (const float*)d_in[4];
    const float* mean_w = (const float*)d_in[5];
    const float* mean_b = (const float*)d_in[6];
    const float* std_w  = (const float*)d_in[7];
    const float* std_b  = (const float*)d_in[8];
    const float* wih0   = (const float*)d_in[9];
    const float* whh0   = (const float*)d_in[10];
    const float* bih0   = (const float*)d_in[11];
    const float* bhh0   = (const float*)d_in[12];
    const float* wih1   = (const float*)d_in[13];
    const float* whh1   = (const float*)d_in[14];
    const float* bih1   = (const float*)d_in[15];
    const float* bhh1   = (const float*)d_in[16];
    float* out = (float*)d_out;

    uint32_t *pwhh0, *pwih0, *pwih1, *pwhh1, *pw1, *pw2, *ph1all, *pd1, *pd2;
    cudaGetSymbolAddress((void**)&pwhh0, g_whh0f);
    cudaGetSymbolAddress((void**)&pwih0, g_wih0f);
    cudaGetSymbolAddress((void**)&pwih1, g_wih1f);
    cudaGetSymbolAddress((void**)&pwhh1, g_whh1f);
    cudaGetSymbolAddress((void**)&pw1, g_w1f);
    cudaGetSymbolAddress((void**)&pw2, g_w2f);
    cudaGetSymbolAddress((void**)&ph1all, g_h1allf);
    cudaGetSymbolAddress((void**)&pd1, g_d1f);
    cudaGetSymbolAddress((void**)&pd2, g_d2f);

    auto blk = [](int n) { return (n + 255) / 256; };
    prepack_w<<<blk(R3_ * R_ / 2), 256>>>(whh0, pwhh0, R3_, R_);
    prepack_w<<<blk(R3_ * Y_ / 2), 256>>>(wih0, pwih0, R3_, Y_);
    prepack_w<<<blk(R3_ * R_ / 2), 256>>>(wih1, pwih1, R3_, R_);
    prepack_w<<<blk(R3_ * R_ / 2), 256>>>(whh1, pwhh1, R3_, R_);
    prepack_w<<<blk(H_ * R_ / 2), 256>>>(dec_w1, pw1, H_, R_);
    prepack_w<<<blk(H_ * H_ / 2), 256>>>(dec_w2, pw2, H_, H_);
    prepack_head<<<blk(64 * H_ / 2), 256>>>(mean_w, std_w);
    prepack_y<<<blk(T_ * B_ * 16), 256>>>(y);
    init_kernel<<<blk(B_ * R_), 256>>>();

    // sequential scan: one persistent kernel (296 blocks = 2/SM)
    rnn_persistent<<<NBLK_, 256>>>(bih0, bhh0, bih1, bhh1);

    // decoder + head over ALL timesteps (single launches)
    dec_gemm<<<dim3(8, MT16_ALL / 8), 256>>>(ph1all, pw1, dec_b1, pd1,
                                             R_ / 16, H_ / 16);
    dec_gemm<<<dim3(8, MT16_ALL / 8), 256>>>(pd1, pw2, dec_b2, pd2,
                                             H_ / 16, H_ / 16);
    head_gemm<<<MT16_ALL / 8, 256>>>(mean_b, std_b);
    nll_kernel<<<T_ * B_ / 8, 256>>>(y);
    reduce_kernel<<<1, 1024>>>(out);
}